// round 15
// baseline (speedup 1.0000x reference)
#include <cuda_runtime.h>
#include <cstdint>

#define D_DIM 128

// ---------------- device scratch: single struct -> one memset ----------------
struct alignas(16) Scratch {
    float  M[D_DIM * D_DIM];            // M = U U^T            (offset 0)
    float  W[D_DIM * D_DIM];            // W = U diag(cnt) U^T  (offset 64KB)
    float  cnt[4096];                   // histogram of G
    double acc;                         // dots accumulator
    double tr;                          // trace(M .* W)
    unsigned mwdone;                    // k_mw blocks finished
    unsigned done;                      // k_dots blocks finished
};
__device__ Scratch g_s;

__device__ __forceinline__ long long ld_idx(const void* p, long long i, int is64) {
    if (is64) return ((const long long*)p)[i];
    return (long long)((const int*)p)[i];
}

// Block-level dtype probe: warp 0 reads first <=32 int64 entries of merge_idx.
// int32 data reinterpreted as int64 has nonzero high words -> out of [0,N).
__device__ __forceinline__ int probe_is64(const void* merge_idx, long long N) {
    __shared__ int s_is64;
    if (threadIdx.x < 32) {
        const long long* p64 = (const long long*)merge_idx;
        int m = (int)(N < 32 ? N : 32);
        int bad = 0;
        if ((int)threadIdx.x < m) {
            long long v = p64[threadIdx.x];
            bad = (v < 0 || v >= N) ? 1 : 0;
        }
        unsigned b = __ballot_sync(0xFFFFFFFFu, bad);
        if (threadIdx.x == 0) s_is64 = (b == 0) ? 1 : 0;
    }
    __syncthreads();
    return s_is64;
}

// ---------------- kernel H: histogram of G (R6-proven) ----------------
__global__ void k_hist(const void* Gp, int total, const void* midx, long long N) {
    int is64 = probe_is64(midx, N);
    int i = blockIdx.x * blockDim.x + threadIdx.x;
    if (i < total) {
        int g = (int)ld_idx(Gp, i, is64);
        atomicAdd(&g_s.cnt[g], 1.0f);
    }
}

// ---------------- kernel MW: M/W build + last-block trace (R6-proven) -------
__global__ void __launch_bounds__(256)
k_mw(const float* __restrict__ U, int P) {
    __shared__ float sh[16][D_DIM];
    __shared__ float shc[16];
    const int tid = threadIdx.x;
    const int bid = blockIdx.x;

    int grp  = bid >> 2;
    int quad = bid & 3;
    int ti = tid & 15, tj = tid >> 4;
    int i0 = (quad & 1) * 64 + ti * 4;
    int j0 = (quad >> 1) * 64 + tj * 4;
    int nchunk = (P + 15) / 16;

    float m[4][4] = {{0}}, w[4][4] = {{0}};
    for (int c = grp; c < nchunk; c += 8) {
        int p0 = c * 16;
        __syncthreads();
        for (int e = tid; e < 16 * D_DIM; e += 256) {
            int d = e >> 4, pc = e & 15;
            int p = p0 + pc;
            sh[pc][d] = (p < P) ? U[(size_t)d * P + p] : 0.f;
        }
        if (tid < 16) {
            int p = p0 + tid;
            shc[tid] = (p < P) ? g_s.cnt[p] : 0.f;
        }
        __syncthreads();
#pragma unroll
        for (int pc = 0; pc < 16; pc++) {
            float cw = shc[pc];
            float a[4], ca[4], b[4];
#pragma unroll
            for (int x = 0; x < 4; x++) { a[x] = sh[pc][i0 + x]; ca[x] = cw * a[x]; }
#pragma unroll
            for (int y = 0; y < 4; y++) b[y] = sh[pc][j0 + y];
#pragma unroll
            for (int x = 0; x < 4; x++)
#pragma unroll
                for (int y = 0; y < 4; y++) {
                    m[x][y] += a[x] * b[y];
                    w[x][y] += ca[x] * b[y];
                }
        }
    }
#pragma unroll
    for (int x = 0; x < 4; x++)
#pragma unroll
        for (int y = 0; y < 4; y++) {
            int idx = (i0 + x) * D_DIM + (j0 + y);
            atomicAdd(&g_s.M[idx], m[x][y]);
            atomicAdd(&g_s.W[idx], w[x][y]);
        }

    // last block: trace(M .* W) -> g_s.tr
    __shared__ int s_last;
    __threadfence();
    if (tid == 0) {
        unsigned t = atomicAdd(&g_s.mwdone, 1u);
        s_last = (t == 31u) ? 1 : 0;
    }
    __syncthreads();
    if (s_last) {
        __threadfence();
        double tr = 0.0;
        int base = tid * 64;
#pragma unroll
        for (int q = 0; q < 16; q++) {
            float4 mv = *(const float4*)(g_s.M + base + q * 4);
            float4 wv = *(const float4*)(g_s.W + base + q * 4);
            tr += (double)mv.x * wv.x + (double)mv.y * wv.y
                + (double)mv.z * wv.z + (double)mv.w * wv.w;
        }
        __shared__ double red[8];
        unsigned mask = 0xFFFFFFFFu;
#pragma unroll
        for (int off = 16; off > 0; off >>= 1)
            tr += __shfl_down_sync(mask, tr, off);
        int lane = tid & 31, warp = tid >> 5;
        if (lane == 0) red[warp] = tr;
        __syncthreads();
        if (warp == 0) {
            double t = (lane < 8) ? red[lane] : 0.0;
#pragma unroll
            for (int off = 4; off > 0; off >>= 1)
                t += __shfl_down_sync(mask, t, off);
            if (lane == 0) g_s.tr = t;
        }
    }
}

// ---------------- kernel D: 4-j/thread float4 dots + inline finalize --------
// LDG-count reduction: per d, 1 float4 ub load + 4 scalar uu loads serve 4 j
// (2.5M warp-LDGs vs 4M scalar). Two paths only; regs capped via launch_bounds.
__global__ void __launch_bounds__(256, 5)
k_dots(const float* __restrict__ Ub, const float* __restrict__ U,
       const void* midx, const void* segs,
       long long N, int P, double inv_den, float* out, int nb) {
    int is64 = probe_is64(midx, N);
    long long j0 = ((long long)blockIdx.x * 256 + threadIdx.x) * 4;

    double val = 0.0;
    if (j0 < N) {
        int npack = (int)((N - j0) < 4 ? (N - j0) : 4);
        long long mi0 = ld_idx(midx, j0, is64);
        int g0 = (int)ld_idx(segs, j0, is64);
        float a0 = 0.f, a1 = 0.f, a2 = 0.f, a3 = 0.f;

        if (npack == 4) {
            long long mi1 = ld_idx(midx, j0 + 1, is64);
            long long mi2 = ld_idx(midx, j0 + 2, is64);
            long long mi3 = ld_idx(midx, j0 + 3, is64);
            int g1 = (int)ld_idx(segs, j0 + 1, is64);
            int g2 = (int)ld_idx(segs, j0 + 2, is64);
            int g3 = (int)ld_idx(segs, j0 + 3, is64);

            bool fast = ((N & 3) == 0) && (mi0 == j0) &&
                        (mi1 == j0 + 1) && (mi2 == j0 + 2) && (mi3 == j0 + 3);
            if (fast) {
                const float* pb = Ub + j0;
                size_t oN = 0, oP = 0;
#pragma unroll 8
                for (int d = 0; d < D_DIM; d++) {
                    float4 v = __ldg((const float4*)(pb + oN));
                    const float* u = U + oP;
                    a0 += v.x * __ldg(u + g0);
                    a1 += v.y * __ldg(u + g1);
                    a2 += v.z * __ldg(u + g2);
                    a3 += v.w * __ldg(u + g3);
                    oN += (size_t)N; oP += (size_t)P;
                }
            } else {
                size_t oN = 0, oP = 0;
#pragma unroll 4
                for (int d = 0; d < D_DIM; d++) {
                    const float* b = Ub + oN;
                    const float* u = U + oP;
                    a0 += __ldg(b + mi0) * __ldg(u + g0);
                    a1 += __ldg(b + mi1) * __ldg(u + g1);
                    a2 += __ldg(b + mi2) * __ldg(u + g2);
                    a3 += __ldg(b + mi3) * __ldg(u + g3);
                    oN += (size_t)N; oP += (size_t)P;
                }
            }
            val = (double)a0 * a0 + (double)a1 * a1
                + (double)a2 * a2 + (double)a3 * a3;
        } else {
            // tail: scalar, per-element
            for (int x = 0; x < npack; x++) {
                long long jj = j0 + x;
                long long mi = ld_idx(midx, jj, is64);
                int g = (int)ld_idx(segs, jj, is64);
                float acc = 0.f;
#pragma unroll 8
                for (int d = 0; d < D_DIM; d++)
                    acc += __ldg(Ub + (size_t)d * N + mi) * __ldg(U + (size_t)d * P + g);
                val += (double)acc * acc;
            }
        }
    }

    // block reduce (256 threads) in double
    __shared__ double red[8];
    __shared__ int s_last;
    if (threadIdx.x == 0) s_last = 0;
    unsigned mask = 0xFFFFFFFFu;
#pragma unroll
    for (int off = 16; off > 0; off >>= 1)
        val += __shfl_down_sync(mask, val, off);
    int lane = threadIdx.x & 31, warp = threadIdx.x >> 5;
    if (lane == 0) red[warp] = val;
    __syncthreads();
    if (warp == 0) {
        double s = (lane < 8) ? red[lane] : 0.0;
#pragma unroll
        for (int off = 4; off > 0; off >>= 1)
            s += __shfl_down_sync(mask, s, off);
        if (lane == 0) {
            atomicAdd(&g_s.acc, s);
            __threadfence();
            unsigned t = atomicAdd(&g_s.done, 1u);
            if (t == (unsigned)nb - 1u) s_last = 1;
        }
    }
    __syncthreads();

    if (s_last && threadIdx.x == 0) {
        __threadfence();
        double dots_total = *(volatile double*)&g_s.acc;
        double tr = *(volatile double*)&g_s.tr;   // written by k_mw (stream order)
        out[0] = (float)(-0.5 * dots_total - 0.5 * tr * inv_den);
    }
}

// ---------------- launch ----------------
extern "C" void kernel_launch(void* const* d_in, const int* in_sizes, int n_in,
                              void* d_out, int out_size) {
    const float* U_base = (const float*)d_in[0];
    const float* U      = (const float*)d_in[1];
    const void*  midx   = d_in[2];
    const void*  segs   = d_in[3];
    const void*  Gp     = d_in[4];

    long long N = in_sizes[2];
    int D = (int)((long long)in_sizes[0] / N); // = 128
    int P = in_sizes[1] / D;                   // = 1024
    int PK = in_sizes[4];                      // P*K
    int K = PK / P;
    (void)D; (void)n_in;

    float* out = (float*)d_out;
    (void)out_size;

    // Zero ALL scratch with one memset node (graph-capturable).
    void* pS;
    cudaGetSymbolAddress(&pS, g_s);
    cudaMemsetAsync(pS, 0, sizeof(Scratch));

    // H: histogram of G
    k_hist<<<(PK + 255) / 256, 256>>>(Gp, PK, midx, N);

    // MW: build M/W + trace in last block
    k_mw<<<32, 256>>>(U, P);

    // D: main pass, 4 j per thread + inline finalize
    long long nblk = (N + 1023) / 1024;
    double inv_den = 1.0 / ((double)P * (double)K * (double)P);
    k_dots<<<(unsigned)nblk, 256>>>(U_base, U, midx, segs, N, P, inv_den, out, (int)nblk);
}

// round 16
// speedup vs baseline: 1.4531x; 1.4531x over previous
#include <cuda_runtime.h>
#include <cstdint>

#define D_DIM 128
#define MAXG 8   // max groups a block may span for the smem fast path

// ---------------- device scratch: single struct -> one memset ----------------
struct alignas(16) Scratch {
    float  M[D_DIM * D_DIM];            // M = U U^T            (offset 0)
    float  W[D_DIM * D_DIM];            // W = U diag(cnt) U^T  (offset 64KB)
    float  cnt[4096];                   // histogram of G
    double acc;                         // dots accumulator
    double tr;                          // trace(M .* W)
    unsigned mwdone;                    // k_mw blocks finished
    unsigned done;                      // k_dots blocks finished
};
__device__ Scratch g_s;

__device__ __forceinline__ long long ld_idx(const void* p, long long i, int is64) {
    if (is64) return ((const long long*)p)[i];
    return (long long)((const int*)p)[i];
}

// Block-level dtype probe: warp 0 reads first <=32 int64 entries of merge_idx.
// int32 data reinterpreted as int64 has nonzero high words -> out of [0,N).
__device__ __forceinline__ int probe_is64(const void* merge_idx, long long N) {
    __shared__ int s_is64;
    if (threadIdx.x < 32) {
        const long long* p64 = (const long long*)merge_idx;
        int m = (int)(N < 32 ? N : 32);
        int bad = 0;
        if ((int)threadIdx.x < m) {
            long long v = p64[threadIdx.x];
            bad = (v < 0 || v >= N) ? 1 : 0;
        }
        unsigned b = __ballot_sync(0xFFFFFFFFu, bad);
        if (threadIdx.x == 0) s_is64 = (b == 0) ? 1 : 0;
    }
    __syncthreads();
    return s_is64;
}

// ---------------- kernel H: histogram of G (R6-proven) ----------------
__global__ void k_hist(const void* Gp, int total, const void* midx, long long N) {
    int is64 = probe_is64(midx, N);
    int i = blockIdx.x * blockDim.x + threadIdx.x;
    if (i < total) {
        int g = (int)ld_idx(Gp, i, is64);
        atomicAdd(&g_s.cnt[g], 1.0f);
    }
}

// ---------------- kernel MW: M/W build + last-block trace (R6-proven) -------
__global__ void __launch_bounds__(256)
k_mw(const float* __restrict__ U, int P) {
    __shared__ float sh[16][D_DIM];
    __shared__ float shc[16];
    const int tid = threadIdx.x;
    const int bid = blockIdx.x;

    int grp  = bid >> 2;
    int quad = bid & 3;
    int ti = tid & 15, tj = tid >> 4;
    int i0 = (quad & 1) * 64 + ti * 4;
    int j0 = (quad >> 1) * 64 + tj * 4;
    int nchunk = (P + 15) / 16;

    float m[4][4] = {{0}}, w[4][4] = {{0}};
    for (int c = grp; c < nchunk; c += 8) {
        int p0 = c * 16;
        __syncthreads();
        for (int e = tid; e < 16 * D_DIM; e += 256) {
            int d = e >> 4, pc = e & 15;
            int p = p0 + pc;
            sh[pc][d] = (p < P) ? U[(size_t)d * P + p] : 0.f;
        }
        if (tid < 16) {
            int p = p0 + tid;
            shc[tid] = (p < P) ? g_s.cnt[p] : 0.f;
        }
        __syncthreads();
#pragma unroll
        for (int pc = 0; pc < 16; pc++) {
            float cw = shc[pc];
            float a[4], ca[4], b[4];
#pragma unroll
            for (int x = 0; x < 4; x++) { a[x] = sh[pc][i0 + x]; ca[x] = cw * a[x]; }
#pragma unroll
            for (int y = 0; y < 4; y++) b[y] = sh[pc][j0 + y];
#pragma unroll
            for (int x = 0; x < 4; x++)
#pragma unroll
                for (int y = 0; y < 4; y++) {
                    m[x][y] += a[x] * b[y];
                    w[x][y] += ca[x] * b[y];
                }
        }
    }
#pragma unroll
    for (int x = 0; x < 4; x++)
#pragma unroll
        for (int y = 0; y < 4; y++) {
            int idx = (i0 + x) * D_DIM + (j0 + y);
            atomicAdd(&g_s.M[idx], m[x][y]);
            atomicAdd(&g_s.W[idx], w[x][y]);
        }

    // last block: trace(M .* W) -> g_s.tr
    __shared__ int s_last;
    __threadfence();
    if (tid == 0) {
        unsigned t = atomicAdd(&g_s.mwdone, 1u);
        s_last = (t == 31u) ? 1 : 0;
    }
    __syncthreads();
    if (s_last) {
        __threadfence();
        double tr = 0.0;
        int base = tid * 64;
#pragma unroll
        for (int q = 0; q < 16; q++) {
            float4 mv = *(const float4*)(g_s.M + base + q * 4);
            float4 wv = *(const float4*)(g_s.W + base + q * 4);
            tr += (double)mv.x * wv.x + (double)mv.y * wv.y
                + (double)mv.z * wv.z + (double)mv.w * wv.w;
        }
        __shared__ double red[8];
        unsigned mask = 0xFFFFFFFFu;
#pragma unroll
        for (int off = 16; off > 0; off >>= 1)
            tr += __shfl_down_sync(mask, tr, off);
        int lane = tid & 31, warp = tid >> 5;
        if (lane == 0) red[warp] = tr;
        __syncthreads();
        if (warp == 0) {
            double t = (lane < 8) ? red[lane] : 0.0;
#pragma unroll
            for (int off = 4; off > 0; off >>= 1)
                t += __shfl_down_sync(mask, t, off);
            if (lane == 0) g_s.tr = t;
        }
    }
}

// ---------------- kernel D: R1 grid/threading + smem-staged U columns -------
// 1954 blocks x 256 threads (proven MLP regime). seg_ids is sorted, so a block
// spans 1-2 groups: stage those U columns in smem once -> inner loop is
// LDG(ub) * LDS(u), halving the warp-LDG count vs R1.
__global__ void __launch_bounds__(256)
k_dots(const float* __restrict__ Ub, const float* __restrict__ U,
       const void* midx, const void* segs,
       long long N, int P, double inv_den, float* out, int nb) {
    const int tid = threadIdx.x;
    int is64 = probe_is64(midx, N);
    long long j = (long long)blockIdx.x * 256 + tid;

    // block's group range (seg_ids sorted)
    __shared__ int s_gmin, s_gw;
    __shared__ float s_u[MAXG * D_DIM];
    if (tid == 0) {
        long long jb = (long long)blockIdx.x * 256;
        if (jb < N) {
            long long je = jb + 255; if (je >= N) je = N - 1;
            int gmin = (int)ld_idx(segs, jb, is64);
            int gmax = (int)ld_idx(segs, je, is64);
            int w = gmax - gmin + 1;
            s_gmin = gmin;
            s_gw = (w >= 1 && w <= MAXG) ? w : 0;
        } else {
            s_gmin = 0; s_gw = 0;
        }
    }
    __syncthreads();
    const int gmin = s_gmin, gw = s_gw;

    if (gw > 0) {
        for (int idx = tid; idx < gw * D_DIM; idx += 256) {
            int grp = idx >> 7, d = idx & 127;
            s_u[idx] = __ldg(U + (size_t)d * P + gmin + grp);
        }
    }
    __syncthreads();

    double val = 0.0;
    if (j < N) {
        long long mi = ld_idx(midx, j, is64);
        int g = (int)ld_idx(segs, j, is64);
        const float* ub = Ub + mi;
        float acc = 0.f;
        if (gw > 0) {
            const float* su = s_u + (g - gmin) * D_DIM;
#pragma unroll 8
            for (int d = 0; d < D_DIM; d++)
                acc += __ldg(ub + (size_t)d * N) * su[d];
        } else {
            const float* uu = U + g;
#pragma unroll 8
            for (int d = 0; d < D_DIM; d++)
                acc += __ldg(ub + (size_t)d * N) * __ldg(uu + (size_t)d * P);
        }
        val = (double)acc * (double)acc;
    }

    // block reduce (256 threads) in double
    __shared__ double red[8];
    __shared__ int s_last;
    if (tid == 0) s_last = 0;
    unsigned mask = 0xFFFFFFFFu;
#pragma unroll
    for (int off = 16; off > 0; off >>= 1)
        val += __shfl_down_sync(mask, val, off);
    int lane = tid & 31, warp = tid >> 5;
    if (lane == 0) red[warp] = val;
    __syncthreads();
    if (warp == 0) {
        double s = (lane < 8) ? red[lane] : 0.0;
#pragma unroll
        for (int off = 4; off > 0; off >>= 1)
            s += __shfl_down_sync(mask, s, off);
        if (lane == 0) {
            atomicAdd(&g_s.acc, s);
            __threadfence();
            unsigned t = atomicAdd(&g_s.done, 1u);
            if (t == (unsigned)nb - 1u) s_last = 1;
        }
    }
    __syncthreads();

    if (s_last && tid == 0) {
        __threadfence();
        double dots_total = *(volatile double*)&g_s.acc;
        double tr = *(volatile double*)&g_s.tr;   // written by k_mw (stream order)
        out[0] = (float)(-0.5 * dots_total - 0.5 * tr * inv_den);
    }
}

// ---------------- launch ----------------
extern "C" void kernel_launch(void* const* d_in, const int* in_sizes, int n_in,
                              void* d_out, int out_size) {
    const float* U_base = (const float*)d_in[0];
    const float* U      = (const float*)d_in[1];
    const void*  midx   = d_in[2];
    const void*  segs   = d_in[3];
    const void*  Gp     = d_in[4];

    long long N = in_sizes[2];
    int D = (int)((long long)in_sizes[0] / N); // = 128
    int P = in_sizes[1] / D;                   // = 1024
    int PK = in_sizes[4];                      // P*K
    int K = PK / P;
    (void)D; (void)n_in;

    float* out = (float*)d_out;
    (void)out_size;

    // Zero ALL scratch with one memset node (graph-capturable).
    void* pS;
    cudaGetSymbolAddress(&pS, g_s);
    cudaMemsetAsync(pS, 0, sizeof(Scratch));

    // H: histogram of G
    k_hist<<<(PK + 255) / 256, 256>>>(Gp, PK, midx, N);

    // MW: build M/W + trace in last block
    k_mw<<<32, 256>>>(U, P);

    // D: main pass (R1 grid, smem-staged U) + inline finalize
    long long nblk = (N + 255) / 256;
    double inv_den = 1.0 / ((double)P * (double)K * (double)P);
    k_dots<<<(unsigned)nblk, 256>>>(U_base, U, midx, segs, N, P, inv_den, out, (int)nblk);
}

// round 17
// speedup vs baseline: 1.4692x; 1.0111x over previous
#include <cuda_runtime.h>
#include <cstdint>

#define D_DIM 128
#define MAXG 8   // max groups a block may span for the smem fast path

// ---------------- device scratch: single struct -> one memset ----------------
struct alignas(16) Scratch {
    float  M[D_DIM * D_DIM];            // M = U U^T            (offset 0)
    float  W[D_DIM * D_DIM];            // W = U diag(cnt) U^T  (offset 64KB)
    float  cnt[4096];                   // histogram of G
    double acc;                         // dots accumulator
    double tr;                          // trace(M .* W)
    unsigned mwdone;                    // k_mw blocks finished
    unsigned done;                      // k_dots blocks finished
};
__device__ Scratch g_s;

__device__ __forceinline__ long long ld_idx(const void* p, long long i, int is64) {
    if (is64) return ((const long long*)p)[i];
    return (long long)((const int*)p)[i];
}

// Block-level dtype probe: warp 0 reads first <=32 int64 entries of merge_idx.
// int32 data reinterpreted as int64 has nonzero high words -> out of [0,N).
__device__ __forceinline__ int probe_is64(const void* merge_idx, long long N) {
    __shared__ int s_is64;
    if (threadIdx.x < 32) {
        const long long* p64 = (const long long*)merge_idx;
        int m = (int)(N < 32 ? N : 32);
        int bad = 0;
        if ((int)threadIdx.x < m) {
            long long v = p64[threadIdx.x];
            bad = (v < 0 || v >= N) ? 1 : 0;
        }
        unsigned b = __ballot_sync(0xFFFFFFFFu, bad);
        if (threadIdx.x == 0) s_is64 = (b == 0) ? 1 : 0;
    }
    __syncthreads();
    return s_is64;
}

// ---------------- kernel H: histogram of G (R6-proven) ----------------
__global__ void k_hist(const void* Gp, int total, const void* midx, long long N) {
    int is64 = probe_is64(midx, N);
    int i = blockIdx.x * blockDim.x + threadIdx.x;
    if (i < total) {
        int g = (int)ld_idx(Gp, i, is64);
        atomicAdd(&g_s.cnt[g], 1.0f);
    }
}

// ---------------- kernel MW: M/W build + last-block trace (R6-proven) -------
__global__ void __launch_bounds__(256)
k_mw(const float* __restrict__ U, int P) {
    __shared__ float sh[16][D_DIM];
    __shared__ float shc[16];
    const int tid = threadIdx.x;
    const int bid = blockIdx.x;

    int grp  = bid >> 2;
    int quad = bid & 3;
    int ti = tid & 15, tj = tid >> 4;
    int i0 = (quad & 1) * 64 + ti * 4;
    int j0 = (quad >> 1) * 64 + tj * 4;
    int nchunk = (P + 15) / 16;

    float m[4][4] = {{0}}, w[4][4] = {{0}};
    for (int c = grp; c < nchunk; c += 8) {
        int p0 = c * 16;
        __syncthreads();
        for (int e = tid; e < 16 * D_DIM; e += 256) {
            int d = e >> 4, pc = e & 15;
            int p = p0 + pc;
            sh[pc][d] = (p < P) ? U[(size_t)d * P + p] : 0.f;
        }
        if (tid < 16) {
            int p = p0 + tid;
            shc[tid] = (p < P) ? g_s.cnt[p] : 0.f;
        }
        __syncthreads();
#pragma unroll
        for (int pc = 0; pc < 16; pc++) {
            float cw = shc[pc];
            float a[4], ca[4], b[4];
#pragma unroll
            for (int x = 0; x < 4; x++) { a[x] = sh[pc][i0 + x]; ca[x] = cw * a[x]; }
#pragma unroll
            for (int y = 0; y < 4; y++) b[y] = sh[pc][j0 + y];
#pragma unroll
            for (int x = 0; x < 4; x++)
#pragma unroll
                for (int y = 0; y < 4; y++) {
                    m[x][y] += a[x] * b[y];
                    w[x][y] += ca[x] * b[y];
                }
        }
    }
#pragma unroll
    for (int x = 0; x < 4; x++)
#pragma unroll
        for (int y = 0; y < 4; y++) {
            int idx = (i0 + x) * D_DIM + (j0 + y);
            atomicAdd(&g_s.M[idx], m[x][y]);
            atomicAdd(&g_s.W[idx], w[x][y]);
        }

    // last block: trace(M .* W) -> g_s.tr
    __shared__ int s_last;
    __threadfence();
    if (tid == 0) {
        unsigned t = atomicAdd(&g_s.mwdone, 1u);
        s_last = (t == 31u) ? 1 : 0;
    }
    __syncthreads();
    if (s_last) {
        __threadfence();
        double tr = 0.0;
        int base = tid * 64;
#pragma unroll
        for (int q = 0; q < 16; q++) {
            float4 mv = *(const float4*)(g_s.M + base + q * 4);
            float4 wv = *(const float4*)(g_s.W + base + q * 4);
            tr += (double)mv.x * wv.x + (double)mv.y * wv.y
                + (double)mv.z * wv.z + (double)mv.w * wv.w;
        }
        __shared__ double red[8];
        unsigned mask = 0xFFFFFFFFu;
#pragma unroll
        for (int off = 16; off > 0; off >>= 1)
            tr += __shfl_down_sync(mask, tr, off);
        int lane = tid & 31, warp = tid >> 5;
        if (lane == 0) red[warp] = tr;
        __syncthreads();
        if (warp == 0) {
            double t = (lane < 8) ? red[lane] : 0.0;
#pragma unroll
            for (int off = 4; off > 0; off >>= 1)
                t += __shfl_down_sync(mask, t, off);
            if (lane == 0) g_s.tr = t;
        }
    }
}

// ---------------- kernel D: 2-j/thread float2 + smem-staged U ---------------
// 977 blocks x 256 threads = 6.6 CTAs/SM: full occupancy retained (R15's 4-j
// failure was occupancy, not packing). Per d: one 256B float2 warp-load (ldcs,
// streaming) + conflict-free LDS. Warp-LDG count: 1M vs R1's 4M.
__global__ void __launch_bounds__(256, 6)
k_dots(const float* __restrict__ Ub, const float* __restrict__ U,
       const void* midx, const void* segs,
       long long N, int P, double inv_den, float* out, int nb) {
    const int tid = threadIdx.x;
    int is64 = probe_is64(midx, N);
    const long long base = (long long)blockIdx.x * 512;   // 512 j per block

    // block group range (seg_ids sorted) + stage U columns to smem
    __shared__ int s_gmin, s_gw;
    __shared__ float s_u[MAXG * D_DIM];
    if (tid == 0) {
        if (base < N) {
            long long je = base + 511; if (je >= N) je = N - 1;
            int gmin = (int)ld_idx(segs, base, is64);
            int gmax = (int)ld_idx(segs, je, is64);
            int w = gmax - gmin + 1;
            s_gmin = gmin;
            s_gw = (w >= 1 && w <= MAXG) ? w : 0;
        } else {
            s_gmin = 0; s_gw = 0;
        }
    }
    __syncthreads();
    const int gmin = s_gmin, gw = s_gw;
    if (gw > 0) {
        for (int idx = tid; idx < gw * D_DIM; idx += 256) {
            int grp = idx >> 7, d = idx & 127;
            s_u[idx] = __ldg(U + (size_t)d * P + gmin + grp);
        }
    }
    __syncthreads();

    double val = 0.0;
    long long j0 = base + (long long)tid * 2;
    if (j0 < N) {
        int npack = (int)((N - j0) < 2 ? (N - j0) : 2);
        long long mi0 = ld_idx(midx, j0, is64);
        int g0 = (int)ld_idx(segs, j0, is64);

        bool fast = false;
        long long mi1 = 0; int g1 = 0;
        if (npack == 2) {
            mi1 = ld_idx(midx, j0 + 1, is64);
            g1 = (int)ld_idx(segs, j0 + 1, is64);
            fast = (gw > 0) && ((N & 1) == 0) && ((mi0 & 1) == 0) && (mi1 == mi0 + 1);
        }

        if (fast) {
            const float2* pb = (const float2*)(Ub + mi0);
            const size_t stride2 = (size_t)(N >> 1);
            const float* su0 = s_u + (g0 - gmin) * D_DIM;
            const float* su1 = s_u + (g1 - gmin) * D_DIM;
            float a0 = 0.f, a1 = 0.f;
#pragma unroll 8
            for (int d = 0; d < D_DIM; d++) {
                float2 v = __ldcs(pb + (size_t)d * stride2);
                a0 += v.x * su0[d];
                a1 += v.y * su1[d];
            }
            val = (double)a0 * a0 + (double)a1 * a1;
        } else {
            // scalar per-j fallback (tails, non-contiguous midx, wide blocks)
            for (int x = 0; x < npack; x++) {
                long long jj = j0 + x;
                long long mi = ld_idx(midx, jj, is64);
                int g = (int)ld_idx(segs, jj, is64);
                const float* ub = Ub + mi;
                float acc = 0.f;
                if (gw > 0) {
                    const float* su = s_u + (g - gmin) * D_DIM;
#pragma unroll 8
                    for (int d = 0; d < D_DIM; d++)
                        acc += __ldg(ub + (size_t)d * N) * su[d];
                } else {
                    const float* uu = U + g;
#pragma unroll 8
                    for (int d = 0; d < D_DIM; d++)
                        acc += __ldg(ub + (size_t)d * N) * __ldg(uu + (size_t)d * P);
                }
                val += (double)acc * acc;
            }
        }
    }

    // block reduce (256 threads) in double
    __shared__ double red[8];
    __shared__ int s_last;
    if (tid == 0) s_last = 0;
    unsigned mask = 0xFFFFFFFFu;
#pragma unroll
    for (int off = 16; off > 0; off >>= 1)
        val += __shfl_down_sync(mask, val, off);
    int lane = tid & 31, warp = tid >> 5;
    if (lane == 0) red[warp] = val;
    __syncthreads();
    if (warp == 0) {
        double s = (lane < 8) ? red[lane] : 0.0;
#pragma unroll
        for (int off = 4; off > 0; off >>= 1)
            s += __shfl_down_sync(mask, s, off);
        if (lane == 0) {
            atomicAdd(&g_s.acc, s);
            __threadfence();
            unsigned t = atomicAdd(&g_s.done, 1u);
            if (t == (unsigned)nb - 1u) s_last = 1;
        }
    }
    __syncthreads();

    if (s_last && tid == 0) {
        __threadfence();
        double dots_total = *(volatile double*)&g_s.acc;
        double tr = *(volatile double*)&g_s.tr;   // written by k_mw (stream order)
        out[0] = (float)(-0.5 * dots_total - 0.5 * tr * inv_den);
    }
}

// ---------------- launch ----------------
extern "C" void kernel_launch(void* const* d_in, const int* in_sizes, int n_in,
                              void* d_out, int out_size) {
    const float* U_base = (const float*)d_in[0];
    const float* U      = (const float*)d_in[1];
    const void*  midx   = d_in[2];
    const void*  segs   = d_in[3];
    const void*  Gp     = d_in[4];

    long long N = in_sizes[2];
    int D = (int)((long long)in_sizes[0] / N); // = 128
    int P = in_sizes[1] / D;                   // = 1024
    int PK = in_sizes[4];                      // P*K
    int K = PK / P;
    (void)D; (void)n_in;

    float* out = (float*)d_out;
    (void)out_size;

    // Zero ALL scratch with one memset node (graph-capturable).
    void* pS;
    cudaGetSymbolAddress(&pS, g_s);
    cudaMemsetAsync(pS, 0, sizeof(Scratch));

    // H: histogram of G
    k_hist<<<(PK + 255) / 256, 256>>>(Gp, PK, midx, N);

    // MW: build M/W + trace in last block
    k_mw<<<32, 256>>>(U, P);

    // D: main pass (2 j/thread, float2 + smem U) + inline finalize
    long long nblk = (N + 511) / 512;
    double inv_den = 1.0 / ((double)P * (double)K * (double)P);
    k_dots<<<(unsigned)nblk, 256>>>(U_base, U, midx, segs, N, P, inv_den, out, (int)nblk);
}